// round 5
// baseline (speedup 1.0000x reference)
#include <cuda_runtime.h>
#include <cuda_bf16.h>

#define B_  128
#define L_  196
#define D_  1024
#define M_  (B_*L_)            // 25088

// ---------------- scratch (device globals; no allocation) ----------------
__device__ float          g_c[B_*D_];        // c[b,e] = att_h + att_x + all 3 biases
__device__ float          g_scores[M_];      // pre-softmax scores
__device__ __nv_bfloat16  g_wa[D_*D_];       // W_a2a in bf16

// ---------------- helpers ----------------
static __device__ __forceinline__ float tanh_fast(float x){
    float y; asm("tanh.approx.f32 %0, %1;" : "=f"(y) : "f"(x)); return y;
}
static __device__ __forceinline__ unsigned smem_u32(const void* p){
    return (unsigned)__cvta_generic_to_shared(p);
}
static __device__ __forceinline__ void ldsm_x4(unsigned r[4], unsigned a){
    asm volatile("ldmatrix.sync.aligned.m8n8.x4.shared.b16 {%0,%1,%2,%3}, [%4];"
        : "=r"(r[0]),"=r"(r[1]),"=r"(r[2]),"=r"(r[3]) : "r"(a));
}
static __device__ __forceinline__ void ldsm_x2(unsigned r[2], unsigned a){
    asm volatile("ldmatrix.sync.aligned.m8n8.x2.shared.b16 {%0,%1}, [%2];"
        : "=r"(r[0]),"=r"(r[1]) : "r"(a));
}
static __device__ __forceinline__ void mma16816(float d[4], const unsigned a[4], const unsigned b[2]){
    asm volatile("mma.sync.aligned.m16n8k16.row.col.f32.bf16.bf16.f32 "
        "{%0,%1,%2,%3}, {%4,%5,%6,%7}, {%8,%9}, {%0,%1,%2,%3};"
        : "+f"(d[0]),"+f"(d[1]),"+f"(d[2]),"+f"(d[3])
        : "r"(a[0]),"r"(a[1]),"r"(a[2]),"r"(a[3]),"r"(b[0]),"r"(b[1]));
}
static __device__ __forceinline__ void cp16(unsigned dst, const void* src){
    asm volatile("cp.async.cg.shared.global [%0], [%1], 16;" :: "r"(dst), "l"(src));
}
static __device__ __forceinline__ void cp_commit(){ asm volatile("cp.async.commit_group;"); }
static __device__ __forceinline__ void cp_wait_all(){ asm volatile("cp.async.wait_all;"); }

// ---------------- kernel 0: W_a2a fp32 -> bf16 ----------------
__global__ __launch_bounds__(256) void k_convert_w(const float* __restrict__ W){
    int i = (blockIdx.x*256 + threadIdx.x)*4;
    float4 v = *reinterpret_cast<const float4*>(W + i);
    *reinterpret_cast<__nv_bfloat162*>(&g_wa[i  ]) = __floats2bfloat162_rn(v.x, v.y);
    *reinterpret_cast<__nv_bfloat162*>(&g_wa[i+2]) = __floats2bfloat162_rn(v.z, v.w);
}

// ---------------- kernel 1: c[b,e] = h@Wh^T + x@Wx^T + (bh+bx+ba) ----------------
__global__ __launch_bounds__(256) void k_cvec(
        const float* __restrict__ h, const float* __restrict__ x,
        const float* __restrict__ Wh, const float* __restrict__ Wx,
        const float* __restrict__ bh, const float* __restrict__ bx,
        const float* __restrict__ ba){
    __shared__ float hs[4][1024];
    __shared__ float xs[4][1024];
    const int tid = threadIdx.x, wid = tid>>5, lane = tid&31;
    const int b0 = blockIdx.x*4;
    for (int i = tid; i < 1024; i += 256){
        int row = i >> 8, c = (i & 255) << 2;
        *reinterpret_cast<float4*>(&hs[row][c]) =
            *reinterpret_cast<const float4*>(h + (size_t)(b0+row)*1024 + c);
        *reinterpret_cast<float4*>(&xs[row][c]) =
            *reinterpret_cast<const float4*>(x + (size_t)(b0+row)*1024 + c);
    }
    __syncthreads();
    const int ebase = blockIdx.y*128 + wid*16;
    for (int ei = 0; ei < 16; ++ei){
        const int e = ebase + ei;
        const float4* wh4 = reinterpret_cast<const float4*>(Wh + (size_t)e*1024);
        const float4* wx4 = reinterpret_cast<const float4*>(Wx + (size_t)e*1024);
        float acc[4] = {0.f,0.f,0.f,0.f};
        #pragma unroll
        for (int it = 0; it < 8; ++it){
            const int d4 = it*32 + lane;
            float4 wv = wh4[d4], xv = wx4[d4];
            #pragma unroll
            for (int b = 0; b < 4; ++b){
                float4 hv = *reinterpret_cast<const float4*>(&hs[b][d4<<2]);
                float4 gv = *reinterpret_cast<const float4*>(&xs[b][d4<<2]);
                acc[b] += wv.x*hv.x + wv.y*hv.y + wv.z*hv.z + wv.w*hv.w;
                acc[b] += xv.x*gv.x + xv.y*gv.y + xv.z*gv.z + xv.w*gv.w;
            }
        }
        #pragma unroll
        for (int b = 0; b < 4; ++b){
            float v = acc[b];
            v += __shfl_xor_sync(0xffffffffu, v, 16);
            v += __shfl_xor_sync(0xffffffffu, v, 8);
            v += __shfl_xor_sync(0xffffffffu, v, 4);
            v += __shfl_xor_sync(0xffffffffu, v, 2);
            v += __shfl_xor_sync(0xffffffffu, v, 1);
            acc[b] = v;
        }
        if (lane < 4){
            float bias = bh[e] + bx[e] + ba[e];
            g_c[(size_t)(b0+lane)*1024 + e] = acc[lane] + bias;
        }
    }
}

// ---------------- kernel 2: fused GEMM + tanh + dot(W_d2d) -> scores ----------------
#define AS_STRIDEB 2064            // 1032 bf16/row: 8-elem pad -> conflict-free ldmatrix
#define BS_OFF     132096          // 64*2064
#define BS_BUF     18432           // 128 * 144
#define BS_STRIDEB 144             // 72 bf16/row
#define CS_OFF     168960          // BS_OFF + 2*BS_BUF
#define WD_OFF     177152          // CS_OFF + 2048*4
#define SC_OFF     181248          // WD_OFF + 1024*4
#define K2_SMEM    181504

__global__ __launch_bounds__(256, 1) void k_scores(
        const float* __restrict__ att, const float* __restrict__ wdd){
    extern __shared__ char sm[];
    const int tid = threadIdx.x, lane = tid & 31, wid = tid >> 5;
    const int m0 = blockIdx.x * 64;
    const int b0 = m0 / L_;
    const unsigned smb = smem_u32(sm);
    float* cs  = reinterpret_cast<float*>(sm + CS_OFF);
    float* wds = reinterpret_cast<float*>(sm + WD_OFF);
    float* ssc = reinterpret_cast<float*>(sm + SC_OFF);

    // ---- A tile (64 x 1024) fp32 -> bf16 smem ----
    {
        const float* ap = att + (size_t)m0 * 1024;
        #pragma unroll 4
        for (int i = 0; i < 64; ++i){
            const int idx = tid + i*256;
            const int row = idx >> 8, c = (idx & 255) << 2;
            float4 v = *reinterpret_cast<const float4*>(ap + (size_t)row*1024 + c);
            char* dst = sm + row*AS_STRIDEB + c*2;
            *reinterpret_cast<__nv_bfloat162*>(dst)   = __floats2bfloat162_rn(v.x, v.y);
            *reinterpret_cast<__nv_bfloat162*>(dst+4) = __floats2bfloat162_rn(v.z, v.w);
        }
    }
    // ---- c rows (<=2 batches per tile), W_d2d, zero score accumulators ----
    {
        int b1 = (m0 + 63) / L_; if (b1 > B_-1) b1 = B_-1;
        for (int i = tid; i < 2048; i += 256){
            int w = i >> 10, e = i & 1023;
            cs[i] = g_c[(size_t)(w ? b1 : b0)*1024 + e];
        }
        for (int i = tid; i < 1024; i += 256) wds[i] = wdd[i];
        if (tid < 64) ssc[tid] = 0.f;
    }

    // per-thread constant addressing
    const int m_off = (wid >> 2) * 32;
    const int n_off = (wid & 3) * 32;
    unsigned a_base[2];
    #pragma unroll
    for (int mt = 0; mt < 2; ++mt)
        a_base[mt] = smb + (unsigned)((m_off + mt*16 + (lane & 15))*AS_STRIDEB
                   + ((lane >> 4) << 4));
    unsigned b_base[4];
    #pragma unroll
    for (int nt = 0; nt < 4; ++nt)
        b_base[nt] = smb + BS_OFF + (unsigned)((n_off + nt*8 + (lane & 7))*BS_STRIDEB
                   + (((lane >> 3) & 1) << 4));
    const float* crow[2][2]; int rowl[2][2];
    #pragma unroll
    for (int mt = 0; mt < 2; ++mt)
        #pragma unroll
        for (int hf = 0; hf < 2; ++hf){
            const int r = m_off + mt*16 + (lane >> 2) + hf*8;
            rowl[mt][hf] = r;
            crow[mt][hf] = cs + (((m0 + r)/L_ != b0) ? 1024 : 0);
        }

    float acc[2][4][4];

    for (int n0 = 0; n0 < 1024; n0 += 128){
        __syncthreads();                     // prior epilogue / B-buffer reads done
        #pragma unroll
        for (int mt = 0; mt < 2; ++mt)
            #pragma unroll
            for (int nt = 0; nt < 4; ++nt)
                #pragma unroll
                for (int i = 0; i < 4; ++i) acc[mt][nt][i] = 0.f;

        // prefetch k-chunk 0 into buffer 0
        #pragma unroll
        for (int i = 0; i < 4; ++i){
            const int idx = tid + i*256, row = idx >> 3, seg = idx & 7;
            cp16(smb + BS_OFF + (unsigned)(row*BS_STRIDEB + seg*16),
                 g_wa + (size_t)(n0 + row)*1024 + seg*8);
        }
        cp_commit();

        for (int kc = 0; kc < 16; ++kc){
            cp_wait_all();
            __syncthreads();                 // buffer kc&1 visible; prior mma done
            if (kc < 15){
                const int buf = (kc+1) & 1, kb = (kc+1)*64;
                #pragma unroll
                for (int i = 0; i < 4; ++i){
                    const int idx = tid + i*256, row = idx >> 3, seg = idx & 7;
                    cp16(smb + BS_OFF + (unsigned)(buf*BS_BUF + row*BS_STRIDEB + seg*16),
                         g_wa + (size_t)(n0 + row)*1024 + kb + seg*8);
                }
                cp_commit();
            }
            const unsigned bufoff = (unsigned)((kc & 1) * BS_BUF);
            #pragma unroll
            for (int ks = 0; ks < 4; ++ks){
                unsigned af[2][4], bf[4][2];
                const unsigned ka = (unsigned)((kc*64 + ks*16) * 2);
                #pragma unroll
                for (int mt = 0; mt < 2; ++mt) ldsm_x4(af[mt], a_base[mt] + ka);
                const unsigned kb2 = bufoff + (unsigned)(ks*32);
                #pragma unroll
                for (int nt = 0; nt < 4; ++nt) ldsm_x2(bf[nt], b_base[nt] + kb2);
                #pragma unroll
                for (int mt = 0; mt < 2; ++mt)
                    #pragma unroll
                    for (int nt = 0; nt < 4; ++nt)
                        mma16816(acc[mt][nt], af[mt], bf[nt]);
            }
        }

        // epilogue: tanh(acc + c)*wd, reduce over this warp's 32 e-cols
        #pragma unroll
        for (int mt = 0; mt < 2; ++mt)
            #pragma unroll
            for (int hf = 0; hf < 2; ++hf){
                float s = 0.f;
                const float* cr = crow[mt][hf];
                #pragma unroll
                for (int nt = 0; nt < 4; ++nt){
                    const int e0 = n0 + n_off + nt*8 + (lane & 3)*2;
                    s += tanh_fast(acc[mt][nt][hf*2+0] + cr[e0  ]) * wds[e0  ];
                    s += tanh_fast(acc[mt][nt][hf*2+1] + cr[e0+1]) * wds[e0+1];
                }
                s += __shfl_xor_sync(0xffffffffu, s, 1);
                s += __shfl_xor_sync(0xffffffffu, s, 2);
                if ((lane & 3) == 0) atomicAdd(&ssc[rowl[mt][hf]], s);
            }
    }
    __syncthreads();
    if (tid < 64) g_scores[m0 + tid] = ssc[tid];   // b_d2d dropped: softmax shift-invariant
}

// ---------------- kernel 3: softmax + weighted sum ----------------
__global__ __launch_bounds__(256) void k_out(const float* __restrict__ att,
                                             float* __restrict__ out){
    __shared__ float w[L_];
    __shared__ float red[256];
    const int b = blockIdx.x, tid = threadIdx.x;
    float s = (tid < L_) ? g_scores[b*L_ + tid] : -1e30f;
    red[tid] = s; __syncthreads();
    #pragma unroll
    for (int o = 128; o > 0; o >>= 1){
        if (tid < o) red[tid] = fmaxf(red[tid], red[tid+o]);
        __syncthreads();
    }
    const float mx = red[0]; __syncthreads();
    const float e = (tid < L_) ? __expf(s - mx) : 0.f;
    red[tid] = e; __syncthreads();
    #pragma unroll
    for (int o = 128; o > 0; o >>= 1){
        if (tid < o) red[tid] += red[tid+o];
        __syncthreads();
    }
    const float inv = 1.f / red[0];
    if (tid < L_) w[tid] = e * inv;
    __syncthreads();

    const float4* ap = reinterpret_cast<const float4*>(att + (size_t)b*L_*1024);
    float4 acc = make_float4(0.f,0.f,0.f,0.f);
    #pragma unroll 4
    for (int l = 0; l < L_; ++l){
        float4 v = ap[l*256 + tid];
        const float wl = w[l];
        acc.x += wl*v.x; acc.y += wl*v.y; acc.z += wl*v.z; acc.w += wl*v.w;
    }
    reinterpret_cast<float4*>(out + (size_t)b*1024)[tid] = acc;
}

// ---------------- launch ----------------
extern "C" void kernel_launch(void* const* d_in, const int* in_sizes, int n_in,
                              void* d_out, int out_size) {
    const float* x   = (const float*)d_in[0];
    const float* att = (const float*)d_in[1];
    const float* h   = (const float*)d_in[2];
    const float* Wa  = (const float*)d_in[3];
    const float* ba  = (const float*)d_in[4];
    const float* Wh  = (const float*)d_in[5];
    const float* bh  = (const float*)d_in[6];
    const float* Wx  = (const float*)d_in[7];
    const float* bx  = (const float*)d_in[8];
    const float* wd  = (const float*)d_in[9];
    float* out = (float*)d_out;

    cudaFuncSetAttribute(k_scores, cudaFuncAttributeMaxDynamicSharedMemorySize, K2_SMEM);

    k_convert_w<<<1024, 256>>>(Wa);
    k_cvec<<<dim3(32, 8), 256>>>(h, x, Wh, Wx, bh, bx, ba);
    k_scores<<<M_/64, 256, K2_SMEM>>>(att, wd);
    k_out<<<B_, 256>>>(att, out);
}

// round 7
// speedup vs baseline: 1.1091x; 1.1091x over previous
#include <cuda_runtime.h>
#include <cuda_bf16.h>
#include <cstdint>

#define B_  128
#define L_  196
#define D_  1024
#define M_  (B_*L_)            // 25088

// ---------------- scratch (device globals; no allocation) ----------------
__device__ float g_c[B_*D_];          // c[b,e] = att_h + att_x + 3 biases
__device__ float g_scores[M_];        // pre-softmax scores
__device__ float g_w[M_];             // softmax weights
__device__ float g_part[4*B_*D_];     // L-split partial outputs (2 MB)
__device__ __nv_bfloat16 g_wa[D_*D_]; // W_a2a bf16

// ---------------- helpers ----------------
static __device__ __forceinline__ float tanh_fast(float x){
    float y; asm("tanh.approx.f32 %0, %1;" : "=f"(y) : "f"(x)); return y;
}
static __device__ __forceinline__ unsigned smem_u32(const void* p){
    return (unsigned)__cvta_generic_to_shared(p);
}
static __device__ __forceinline__ void ldsm_x4(unsigned r[4], unsigned a){
    asm volatile("ldmatrix.sync.aligned.m8n8.x4.shared.b16 {%0,%1,%2,%3}, [%4];"
        : "=r"(r[0]),"=r"(r[1]),"=r"(r[2]),"=r"(r[3]) : "r"(a));
}
static __device__ __forceinline__ void ldsm_x2(unsigned r[2], unsigned a){
    asm volatile("ldmatrix.sync.aligned.m8n8.x2.shared.b16 {%0,%1}, [%2];"
        : "=r"(r[0]),"=r"(r[1]) : "r"(a));
}
static __device__ __forceinline__ void mma16816(float d[4], const unsigned a[4], const unsigned b[2]){
    asm volatile("mma.sync.aligned.m16n8k16.row.col.f32.bf16.bf16.f32 "
        "{%0,%1,%2,%3}, {%4,%5,%6,%7}, {%8,%9}, {%0,%1,%2,%3};"
        : "+f"(d[0]),"+f"(d[1]),"+f"(d[2]),"+f"(d[3])
        : "r"(a[0]),"r"(a[1]),"r"(a[2]),"r"(a[3]),"r"(b[0]),"r"(b[1]));
}
static __device__ __forceinline__ void cp16(unsigned dst, const void* src){
    asm volatile("cp.async.cg.shared.global [%0], [%1], 16;" :: "r"(dst), "l"(src));
}
static __device__ __forceinline__ void cp_commit(){ asm volatile("cp.async.commit_group;"); }
static __device__ __forceinline__ void cp_wait0(){
    asm volatile("cp.async.wait_group 0;" ::: "memory");
}

// ---------------- kernel 0: W_a2a fp32 -> bf16 ----------------
__global__ __launch_bounds__(256) void k_convert_w(const float* __restrict__ W){
    int i = (blockIdx.x*256 + threadIdx.x)*4;
    float4 v = *reinterpret_cast<const float4*>(W + i);
    *reinterpret_cast<__nv_bfloat162*>(&g_wa[i  ]) = __floats2bfloat162_rn(v.x, v.y);
    *reinterpret_cast<__nv_bfloat162*>(&g_wa[i+2]) = __floats2bfloat162_rn(v.z, v.w);
}

// ---------------- kernel 1: c[b,e] = h@Wh^T + x@Wx^T + (bh+bx+ba) ----------------
__global__ __launch_bounds__(256) void k_cvec(
        const float* __restrict__ h, const float* __restrict__ x,
        const float* __restrict__ Wh, const float* __restrict__ Wx,
        const float* __restrict__ bh, const float* __restrict__ bx,
        const float* __restrict__ ba){
    __shared__ float hs[4][1024];
    __shared__ float xs[4][1024];
    const int tid = threadIdx.x, wid = tid>>5, lane = tid&31;
    const int b0 = blockIdx.x*4;
    for (int i = tid; i < 1024; i += 256){
        int row = i >> 8, c = (i & 255) << 2;
        *reinterpret_cast<float4*>(&hs[row][c]) =
            *reinterpret_cast<const float4*>(h + (size_t)(b0+row)*1024 + c);
        *reinterpret_cast<float4*>(&xs[row][c]) =
            *reinterpret_cast<const float4*>(x + (size_t)(b0+row)*1024 + c);
    }
    __syncthreads();
    const int ebase = blockIdx.y*128 + wid*16;
    for (int ei = 0; ei < 16; ++ei){
        const int e = ebase + ei;
        const float4* wh4 = reinterpret_cast<const float4*>(Wh + (size_t)e*1024);
        const float4* wx4 = reinterpret_cast<const float4*>(Wx + (size_t)e*1024);
        float acc[4] = {0.f,0.f,0.f,0.f};
        #pragma unroll
        for (int it = 0; it < 8; ++it){
            const int d4 = it*32 + lane;
            float4 wv = wh4[d4], xv = wx4[d4];
            #pragma unroll
            for (int b = 0; b < 4; ++b){
                float4 hv = *reinterpret_cast<const float4*>(&hs[b][d4<<2]);
                float4 gv = *reinterpret_cast<const float4*>(&xs[b][d4<<2]);
                acc[b] += wv.x*hv.x + wv.y*hv.y + wv.z*hv.z + wv.w*hv.w;
                acc[b] += xv.x*gv.x + xv.y*gv.y + xv.z*gv.z + xv.w*gv.w;
            }
        }
        #pragma unroll
        for (int b = 0; b < 4; ++b){
            float v = acc[b];
            v += __shfl_xor_sync(0xffffffffu, v, 16);
            v += __shfl_xor_sync(0xffffffffu, v, 8);
            v += __shfl_xor_sync(0xffffffffu, v, 4);
            v += __shfl_xor_sync(0xffffffffu, v, 2);
            v += __shfl_xor_sync(0xffffffffu, v, 1);
            acc[b] = v;
        }
        if (lane < 4){
            float bias = bh[e] + bx[e] + ba[e];
            g_c[(size_t)(b0+lane)*1024 + e] = acc[lane] + bias;
        }
    }
}

// ---------------- kernel 2: fused GEMM + tanh + dot(W_d2d) -> scores ----------------
// CTA = 64 att rows, full K=1024 resident. Flat 64-step pipeline:
// step s: n-chunk s>>3 (128 cols), k-chunk s&7 (128 k). B double-buffered cp.async.
#define AS_STRIDEB 2064            // 1032 bf16/row (8-elem pad, conflict-free ldsm)
#define B_OFF      132096          // 64*2064
#define BBUF       34816           // 128 rows * 272B
#define BS_STRIDEB 272             // 136 bf16/row (8-elem pad)
#define CS_OFF     201728          // B_OFF + 2*BBUF
#define WD_OFF     209920          // CS_OFF + 2048*4
#define SSC_OFF    214016          // WD_OFF + 1024*4
#define SM_SZ      214272

__global__ __launch_bounds__(256, 1) void k_scores(
        const float* __restrict__ att, const float* __restrict__ wdd){
    extern __shared__ char sm[];
    const int tid = threadIdx.x, lane = tid & 31, wid = tid >> 5;
    const int m0 = blockIdx.x * 64;
    const int b0 = m0 / L_;
    const unsigned smb = smem_u32(sm);
    float* cs  = reinterpret_cast<float*>(sm + CS_OFF);
    float* wds = reinterpret_cast<float*>(sm + WD_OFF);
    float* ssc = reinterpret_cast<float*>(sm + SSC_OFF);

    // ---- A tile (64 x 1024) fp32 -> bf16 smem (once) ----
    {
        const float* ap = att + (size_t)m0 * 1024;
        #pragma unroll 4
        for (int i = 0; i < 64; ++i){
            const int idx = tid + i*256;
            const int row = idx >> 8, c = (idx & 255) << 2;
            float4 v = *reinterpret_cast<const float4*>(ap + (size_t)row*1024 + c);
            char* dst = sm + row*AS_STRIDEB + c*2;
            *reinterpret_cast<__nv_bfloat162*>(dst)   = __floats2bfloat162_rn(v.x, v.y);
            *reinterpret_cast<__nv_bfloat162*>(dst+4) = __floats2bfloat162_rn(v.z, v.w);
        }
    }
    // ---- c rows (<=2 batches per tile), W_d2d, zero score accumulators ----
    {
        int b1 = (m0 + 63) / L_; if (b1 > B_-1) b1 = B_-1;
        for (int i = tid; i < 2048; i += 256){
            int w = i >> 10, e = i & 1023;
            cs[i] = g_c[(size_t)(w ? b1 : b0)*1024 + e];
        }
        for (int i = tid; i < 1024; i += 256) wds[i] = wdd[i];
        if (tid < 64) ssc[tid] = 0.f;
    }

    // per-thread constant addressing (warp grid: 2 m x 4 n, warp tile 32x32)
    const int m_off = (wid >> 2) * 32;
    const int n_off = (wid & 3) * 32;
    unsigned a_base[2];
    #pragma unroll
    for (int mt = 0; mt < 2; ++mt)
        a_base[mt] = smb + (unsigned)((m_off + mt*16 + (lane & 15))*AS_STRIDEB
                   + ((lane >> 4) << 4));
    unsigned b_base[4];
    #pragma unroll
    for (int nt = 0; nt < 4; ++nt)
        b_base[nt] = smb + B_OFF + (unsigned)((n_off + nt*8 + (lane & 7))*BS_STRIDEB
                   + (((lane >> 3) & 1) << 4));
    const float* crow[2][2]; int rowl[2][2];
    #pragma unroll
    for (int mt = 0; mt < 2; ++mt)
        #pragma unroll
        for (int hf = 0; hf < 2; ++hf){
            const int r = m_off + mt*16 + (lane >> 2) + hf*8;
            rowl[mt][hf] = r;
            crow[mt][hf] = cs + (((m0 + r)/L_ != b0) ? 1024 : 0);
        }

    // B stage loader: step t covers n-chunk (t>>3)*128, k-chunk (t&7)*128
    auto load_step = [&](int t, int buf){
        const int n0 = (t >> 3) * 128, kk = (t & 7) * 128;
        #pragma unroll
        for (int i = 0; i < 8; ++i){
            const int idx = tid + i*256;         // 0..2047
            const int row = idx >> 4, seg = idx & 15;
            cp16(smb + B_OFF + (unsigned)(buf*BBUF + row*BS_STRIDEB + seg*16),
                 g_wa + (size_t)(n0 + row)*1024 + kk + seg*8);
        }
    };

    float acc[2][4][4];
    load_step(0, 0);
    cp_commit();

    for (int s = 0; s < 64; ++s){
        const int kch = s & 7;
        cp_wait0();                  // step-s B data arrived
        __syncthreads();             // ...and all warps done reading buffer (s+1)&1
        if (s < 63){ load_step(s+1, (s+1)&1); cp_commit(); }

        if (kch == 0){
            #pragma unroll
            for (int mt = 0; mt < 2; ++mt)
                #pragma unroll
                for (int nt = 0; nt < 4; ++nt)
                    #pragma unroll
                    for (int i = 0; i < 4; ++i) acc[mt][nt][i] = 0.f;
        }
        const unsigned bufo = (unsigned)((s & 1) * BBUF);
        #pragma unroll
        for (int ks = 0; ks < 8; ++ks){
            unsigned af[2][4], bf[4][2];
            const unsigned ka = (unsigned)((kch*128 + ks*16) * 2);
            #pragma unroll
            for (int mt = 0; mt < 2; ++mt) ldsm_x4(af[mt], a_base[mt] + ka);
            const unsigned kb = bufo + (unsigned)(ks*32);
            #pragma unroll
            for (int nt = 0; nt < 4; ++nt) ldsm_x2(bf[nt], b_base[nt] + kb);
            #pragma unroll
            for (int mt = 0; mt < 2; ++mt)
                #pragma unroll
                for (int nt = 0; nt < 4; ++nt)
                    mma16816(acc[mt][nt], af[mt], bf[nt]);
        }

        if (kch == 7){   // n-chunk done: fused epilogue (registers only, no barrier)
            const int n0 = (s >> 3) * 128;
            #pragma unroll
            for (int mt = 0; mt < 2; ++mt)
                #pragma unroll
                for (int hf = 0; hf < 2; ++hf){
                    float v = 0.f;
                    const float* cr = crow[mt][hf];
                    #pragma unroll
                    for (int nt = 0; nt < 4; ++nt){
                        const int e0 = n0 + n_off + nt*8 + (lane & 3)*2;
                        v += tanh_fast(acc[mt][nt][hf*2+0] + cr[e0  ]) * wds[e0  ];
                        v += tanh_fast(acc[mt][nt][hf*2+1] + cr[e0+1]) * wds[e0+1];
                    }
                    v += __shfl_xor_sync(0xffffffffu, v, 1);
                    v += __shfl_xor_sync(0xffffffffu, v, 2);
                    if ((lane & 3) == 0) atomicAdd(&ssc[rowl[mt][hf]], v);
                }
        }
    }
    __syncthreads();
    if (tid < 64) g_scores[m0 + tid] = ssc[tid];   // b_d2d dropped (softmax shift-invariant)
}

// ---------------- kernel 3a: softmax -> g_w ----------------
__global__ __launch_bounds__(256) void k_soft(){
    __shared__ float red[256];
    const int b = blockIdx.x, tid = threadIdx.x;
    const float s = (tid < L_) ? g_scores[b*L_ + tid] : -1e30f;
    red[tid] = s; __syncthreads();
    #pragma unroll
    for (int o = 128; o > 0; o >>= 1){
        if (tid < o) red[tid] = fmaxf(red[tid], red[tid+o]);
        __syncthreads();
    }
    const float mx = red[0]; __syncthreads();
    const float e = (tid < L_) ? __expf(s - mx) : 0.f;
    red[tid] = e; __syncthreads();
    #pragma unroll
    for (int o = 128; o > 0; o >>= 1){
        if (tid < o) red[tid] += red[tid+o];
        __syncthreads();
    }
    if (tid < L_) g_w[b*L_ + tid] = e / red[0];
}

// ---------------- kernel 3b: L-split weighted partial sums ----------------
__global__ __launch_bounds__(256) void k_outp(const float* __restrict__ att){
    __shared__ float w[49];
    const int b = blockIdx.x, q = blockIdx.y, tid = threadIdx.x;
    if (tid < 49) w[tid] = g_w[b*L_ + q*49 + tid];
    __syncthreads();
    const float4* ap = reinterpret_cast<const float4*>(att)
                     + (size_t)b*L_*256 + (size_t)q*49*256 + tid;
    float4 acc = make_float4(0.f,0.f,0.f,0.f);
    #pragma unroll 7
    for (int l = 0; l < 49; ++l){
        float4 v = ap[(size_t)l*256];
        const float wl = w[l];
        acc.x += wl*v.x; acc.y += wl*v.y; acc.z += wl*v.z; acc.w += wl*v.w;
    }
    reinterpret_cast<float4*>(g_part)[((size_t)q*B_ + b)*256 + tid] = acc;
}

// ---------------- kernel 3c: combine quarters ----------------
__global__ __launch_bounds__(256) void k_out2(float* __restrict__ out){
    const int b = blockIdx.x, tid = threadIdx.x;
    const float4* p = reinterpret_cast<const float4*>(g_part);
    float4 a0 = p[((size_t)0*B_ + b)*256 + tid];
    float4 a1 = p[((size_t)1*B_ + b)*256 + tid];
    float4 a2 = p[((size_t)2*B_ + b)*256 + tid];
    float4 a3 = p[((size_t)3*B_ + b)*256 + tid];
    float4 r;
    r.x = (a0.x + a1.x) + (a2.x + a3.x);
    r.y = (a0.y + a1.y) + (a2.y + a3.y);
    r.z = (a0.z + a1.z) + (a2.z + a3.z);
    r.w = (a0.w + a1.w) + (a2.w + a3.w);
    reinterpret_cast<float4*>(out)[(size_t)b*256 + tid] = r;
}

// ---------------- launch ----------------
extern "C" void kernel_launch(void* const* d_in, const int* in_sizes, int n_in,
                              void* d_out, int out_size) {
    const float* x   = (const float*)d_in[0];
    const float* att = (const float*)d_in[1];
    const float* h   = (const float*)d_in[2];
    const float* Wa  = (const float*)d_in[3];
    const float* ba  = (const float*)d_in[4];
    const float* Wh  = (const float*)d_in[5];
    const float* bh  = (const float*)d_in[6];
    const float* Wx  = (const float*)d_in[7];
    const float* bx  = (const float*)d_in[8];
    const float* wd  = (const float*)d_in[9];
    float* out = (float*)d_out;

    cudaFuncSetAttribute(k_scores, cudaFuncAttributeMaxDynamicSharedMemorySize, SM_SZ);

    k_convert_w<<<1024, 256>>>(Wa);
    k_cvec<<<dim3(32, 8), 256>>>(h, x, Wh, Wx, bh, bx, ba);
    k_scores<<<M_/64, 256, SM_SZ>>>(att, wd);
    k_soft<<<B_, 256>>>();
    k_outp<<<dim3(B_, 4), 256>>>(att);
    k_out2<<<B_, 256>>>(out);
}

// round 8
// speedup vs baseline: 1.1508x; 1.0376x over previous
#include <cuda_runtime.h>
#include <cuda_bf16.h>
#include <cstdint>

#define B_  128
#define L_  196
#define D_  1024
#define M_  (B_*L_)            // 25088

// ---------------- scratch (device globals; no allocation) ----------------
__device__ float g_c[B_*D_];          // c[b,e] = att_h + att_x + 3 biases
__device__ float g_scores[M_];        // pre-softmax scores
__device__ float g_part[7*B_*D_];     // L-split partial outputs (3.5 MB)
__device__ __nv_bfloat16 g_wa[D_*D_]; // W_a2a bf16

// ---------------- helpers ----------------
static __device__ __forceinline__ float tanh_fast(float x){
    float y; asm("tanh.approx.f32 %0, %1;" : "=f"(y) : "f"(x)); return y;
}
static __device__ __forceinline__ unsigned smem_u32(const void* p){
    return (unsigned)__cvta_generic_to_shared(p);
}
static __device__ __forceinline__ void ldsm_x4(unsigned r[4], unsigned a){
    asm volatile("ldmatrix.sync.aligned.m8n8.x4.shared.b16 {%0,%1,%2,%3}, [%4];"
        : "=r"(r[0]),"=r"(r[1]),"=r"(r[2]),"=r"(r[3]) : "r"(a));
}
static __device__ __forceinline__ void ldsm_x2(unsigned r[2], unsigned a){
    asm volatile("ldmatrix.sync.aligned.m8n8.x2.shared.b16 {%0,%1}, [%2];"
        : "=r"(r[0]),"=r"(r[1]) : "r"(a));
}
static __device__ __forceinline__ void mma16816(float d[4], const unsigned a[4], const unsigned b[2]){
    asm volatile("mma.sync.aligned.m16n8k16.row.col.f32.bf16.bf16.f32 "
        "{%0,%1,%2,%3}, {%4,%5,%6,%7}, {%8,%9}, {%0,%1,%2,%3};"
        : "+f"(d[0]),"+f"(d[1]),"+f"(d[2]),"+f"(d[3])
        : "r"(a[0]),"r"(a[1]),"r"(a[2]),"r"(a[3]),"r"(b[0]),"r"(b[1]));
}
static __device__ __forceinline__ void cp16(unsigned dst, const void* src){
    asm volatile("cp.async.cg.shared.global [%0], [%1], 16;" :: "r"(dst), "l"(src));
}
static __device__ __forceinline__ void cp_commit(){ asm volatile("cp.async.commit_group;"); }
static __device__ __forceinline__ void cp_wait0(){
    asm volatile("cp.async.wait_group 0;" ::: "memory");
}

// ---------------- kernel 0: W_a2a fp32 -> bf16 ----------------
__global__ __launch_bounds__(256) void k_convert_w(const float* __restrict__ W){
    int i = (blockIdx.x*256 + threadIdx.x)*4;
    float4 v = *reinterpret_cast<const float4*>(W + i);
    *reinterpret_cast<__nv_bfloat162*>(&g_wa[i  ]) = __floats2bfloat162_rn(v.x, v.y);
    *reinterpret_cast<__nv_bfloat162*>(&g_wa[i+2]) = __floats2bfloat162_rn(v.z, v.w);
}

// ---------------- kernel 1: c[b,e] = h@Wh^T + x@Wx^T + (bh+bx+ba) ----------------
__global__ __launch_bounds__(256) void k_cvec(
        const float* __restrict__ h, const float* __restrict__ x,
        const float* __restrict__ Wh, const float* __restrict__ Wx,
        const float* __restrict__ bh, const float* __restrict__ bx,
        const float* __restrict__ ba){
    __shared__ float hs[4][1024];
    __shared__ float xs[4][1024];
    const int tid = threadIdx.x, wid = tid>>5, lane = tid&31;
    const int b0 = blockIdx.x*4;
    for (int i = tid; i < 1024; i += 256){
        int row = i >> 8, c = (i & 255) << 2;
        *reinterpret_cast<float4*>(&hs[row][c]) =
            *reinterpret_cast<const float4*>(h + (size_t)(b0+row)*1024 + c);
        *reinterpret_cast<float4*>(&xs[row][c]) =
            *reinterpret_cast<const float4*>(x + (size_t)(b0+row)*1024 + c);
    }
    __syncthreads();
    const int ebase = blockIdx.y*128 + wid*16;
    for (int ei = 0; ei < 16; ++ei){
        const int e = ebase + ei;
        const float4* wh4 = reinterpret_cast<const float4*>(Wh + (size_t)e*1024);
        const float4* wx4 = reinterpret_cast<const float4*>(Wx + (size_t)e*1024);
        float acc[4] = {0.f,0.f,0.f,0.f};
        #pragma unroll
        for (int it = 0; it < 8; ++it){
            const int d4 = it*32 + lane;
            float4 wv = wh4[d4], xv = wx4[d4];
            #pragma unroll
            for (int b = 0; b < 4; ++b){
                float4 hv = *reinterpret_cast<const float4*>(&hs[b][d4<<2]);
                float4 gv = *reinterpret_cast<const float4*>(&xs[b][d4<<2]);
                acc[b] += wv.x*hv.x + wv.y*hv.y + wv.z*hv.z + wv.w*hv.w;
                acc[b] += xv.x*gv.x + xv.y*gv.y + xv.z*gv.z + xv.w*gv.w;
            }
        }
        #pragma unroll
        for (int b = 0; b < 4; ++b){
            float v = acc[b];
            v += __shfl_xor_sync(0xffffffffu, v, 16);
            v += __shfl_xor_sync(0xffffffffu, v, 8);
            v += __shfl_xor_sync(0xffffffffu, v, 4);
            v += __shfl_xor_sync(0xffffffffu, v, 2);
            v += __shfl_xor_sync(0xffffffffu, v, 1);
            acc[b] = v;
        }
        if (lane < 4){
            float bias = bh[e] + bx[e] + ba[e];
            g_c[(size_t)(b0+lane)*1024 + e] = acc[lane] + bias;
        }
    }
}

// ---------------- kernel 2: fused GEMM + tanh + dot(W_d2d) -> scores ----------------
// 512 threads (16 warps, 4/SMSP). CTA = 64 att rows, full K=1024 resident.
// Flat 64-step pipeline: step s -> n-chunk (s>>4)*256, k-chunk (s&15)*64.
// Warp grid 2(m)x8(n), warp tile 32x32. B double-buffered cp.async.
#define AS_STRIDEB 2064            // 1032 bf16/row (8-elem pad, conflict-free ldsm)
#define B_OFF      132096          // 64*2064
#define BBUF       36864           // 256 rows * 144B
#define BS_STRIDEB 144             // 72 bf16/row (8-elem pad)
#define CS_OFF     205824          // B_OFF + 2*BBUF
#define WD_OFF     214016          // CS_OFF + 2048*4
#define SSC_OFF    218112          // WD_OFF + 1024*4
#define SM_SZ      218368

__global__ __launch_bounds__(512, 1) void k_scores(
        const float* __restrict__ att, const float* __restrict__ wdd){
    extern __shared__ char sm[];
    const int tid = threadIdx.x, lane = tid & 31, wid = tid >> 5;
    const int m0 = blockIdx.x * 64;
    const int b0 = m0 / L_;
    const unsigned smb = smem_u32(sm);
    float* cs  = reinterpret_cast<float*>(sm + CS_OFF);
    float* wds = reinterpret_cast<float*>(sm + WD_OFF);
    float* ssc = reinterpret_cast<float*>(sm + SSC_OFF);

    // ---- A tile (64 x 1024) fp32 -> bf16 smem (once) ----
    {
        const float* ap = att + (size_t)m0 * 1024;
        #pragma unroll 4
        for (int i = 0; i < 32; ++i){
            const int idx = tid + i*512;
            const int row = idx >> 8, c = (idx & 255) << 2;
            float4 v = *reinterpret_cast<const float4*>(ap + (size_t)row*1024 + c);
            char* dst = sm + row*AS_STRIDEB + c*2;
            *reinterpret_cast<__nv_bfloat162*>(dst)   = __floats2bfloat162_rn(v.x, v.y);
            *reinterpret_cast<__nv_bfloat162*>(dst+4) = __floats2bfloat162_rn(v.z, v.w);
        }
    }
    // ---- c rows (<=2 batches per tile), W_d2d, zero score accumulators ----
    {
        int b1 = (m0 + 63) / L_; if (b1 > B_-1) b1 = B_-1;
        for (int i = tid; i < 2048; i += 512){
            int w = i >> 10, e = i & 1023;
            cs[i] = g_c[(size_t)(w ? b1 : b0)*1024 + e];
        }
        for (int i = tid; i < 1024; i += 512) wds[i] = wdd[i];
        if (tid < 64) ssc[tid] = 0.f;
    }

    // warp mapping: m_off in {0,32}, n_off in {0..224} within the 256-wide n-chunk
    const int m_off = (wid >> 3) * 32;
    const int n_off = (wid & 7) * 32;
    unsigned a_base[2];
    #pragma unroll
    for (int mt = 0; mt < 2; ++mt)
        a_base[mt] = smb + (unsigned)((m_off + mt*16 + (lane & 15))*AS_STRIDEB
                   + ((lane >> 4) << 4));
    unsigned b_base[4];
    #pragma unroll
    for (int nt = 0; nt < 4; ++nt)
        b_base[nt] = smb + B_OFF + (unsigned)((n_off + nt*8 + (lane & 7))*BS_STRIDEB
                   + (((lane >> 3) & 1) << 4));
    const float* crow[2][2]; int rowl[2][2];
    #pragma unroll
    for (int mt = 0; mt < 2; ++mt)
        #pragma unroll
        for (int hf = 0; hf < 2; ++hf){
            const int r = m_off + mt*16 + (lane >> 2) + hf*8;
            rowl[mt][hf] = r;
            crow[mt][hf] = cs + (((m0 + r)/L_ != b0) ? 1024 : 0);
        }

    // B stage loader: step t -> n-chunk (t>>4)*256 rows, k-chunk (t&15)*64
    auto load_step = [&](int t, int buf){
        const int n0 = (t >> 4) * 256, kk = (t & 15) * 64;
        #pragma unroll
        for (int i = 0; i < 4; ++i){
            const int idx = tid + i*512;         // 0..2047 -> 256 rows x 8 segs
            const int row = idx >> 3, seg = idx & 7;
            cp16(smb + B_OFF + (unsigned)(buf*BBUF + row*BS_STRIDEB + seg*16),
                 g_wa + (size_t)(n0 + row)*1024 + kk + seg*8);
        }
    };

    float acc[2][4][4];
    load_step(0, 0);
    cp_commit();

    for (int s = 0; s < 64; ++s){
        const int kch = s & 15;
        cp_wait0();                  // step-s B data arrived
        __syncthreads();             // ...and all warps done reading buffer (s+1)&1
        if (s < 63){ load_step(s+1, (s+1)&1); cp_commit(); }

        if (kch == 0){
            #pragma unroll
            for (int mt = 0; mt < 2; ++mt)
                #pragma unroll
                for (int nt = 0; nt < 4; ++nt)
                    #pragma unroll
                    for (int i = 0; i < 4; ++i) acc[mt][nt][i] = 0.f;
        }
        const unsigned bufo = (unsigned)((s & 1) * BBUF);
        #pragma unroll
        for (int ks = 0; ks < 4; ++ks){
            unsigned af[2][4], bf[4][2];
            const unsigned ka = (unsigned)((kch*64 + ks*16) * 2);
            #pragma unroll
            for (int mt = 0; mt < 2; ++mt) ldsm_x4(af[mt], a_base[mt] + ka);
            const unsigned kb = bufo + (unsigned)(ks*32);
            #pragma unroll
            for (int nt = 0; nt < 4; ++nt) ldsm_x2(bf[nt], b_base[nt] + kb);
            #pragma unroll
            for (int mt = 0; mt < 2; ++mt)
                #pragma unroll
                for (int nt = 0; nt < 4; ++nt)
                    mma16816(acc[mt][nt], af[mt], bf[nt]);
        }

        if (kch == 15){   // n-chunk done: fused epilogue
            const int n0 = (s >> 4) * 256;
            #pragma unroll
            for (int mt = 0; mt < 2; ++mt)
                #pragma unroll
                for (int hf = 0; hf < 2; ++hf){
                    float v = 0.f;
                    const float* cr = crow[mt][hf];
                    #pragma unroll
                    for (int nt = 0; nt < 4; ++nt){
                        const int e0 = n0 + n_off + nt*8 + (lane & 3)*2;
                        v += tanh_fast(acc[mt][nt][hf*2+0] + cr[e0  ]) * wds[e0  ];
                        v += tanh_fast(acc[mt][nt][hf*2+1] + cr[e0+1]) * wds[e0+1];
                    }
                    v += __shfl_xor_sync(0xffffffffu, v, 1);
                    v += __shfl_xor_sync(0xffffffffu, v, 2);
                    if ((lane & 3) == 0) atomicAdd(&ssc[rowl[mt][hf]], v);
                }
        }
    }
    __syncthreads();
    if (tid < 64) g_scores[m0 + tid] = ssc[tid];   // b_d2d dropped (softmax shift-invariant)
}

// ---------------- kernel 3a: softmax + L-split(7) weighted partial sums ----------------
__global__ __launch_bounds__(256) void k_outp(const float* __restrict__ att){
    __shared__ float sc[256];
    __shared__ float red[256];
    const int b = blockIdx.x, q = blockIdx.y, tid = threadIdx.x;
    const float s = (tid < L_) ? g_scores[b*L_ + tid] : -1e30f;
    red[tid] = s; __syncthreads();
    #pragma unroll
    for (int o = 128; o > 0; o >>= 1){
        if (tid < o) red[tid] = fmaxf(red[tid], red[tid+o]);
        __syncthreads();
    }
    const float mx = red[0]; __syncthreads();
    const float e = (tid < L_) ? __expf(s - mx) : 0.f;
    sc[tid] = e; red[tid] = e; __syncthreads();
    #pragma unroll
    for (int o = 128; o > 0; o >>= 1){
        if (tid < o) red[tid] += red[tid+o];
        __syncthreads();
    }
    const float inv = 1.f / red[0];
    __syncthreads();

    const float4* ap = reinterpret_cast<const float4*>(att)
                     + (size_t)b*L_*256 + (size_t)q*28*256 + tid;
    float4 acc = make_float4(0.f,0.f,0.f,0.f);
    #pragma unroll 7
    for (int l = 0; l < 28; ++l){
        float4 v = ap[(size_t)l*256];
        const float wl = sc[q*28 + l] * inv;
        acc.x += wl*v.x; acc.y += wl*v.y; acc.z += wl*v.z; acc.w += wl*v.w;
    }
    reinterpret_cast<float4*>(g_part)[((size_t)q*B_ + b)*256 + tid] = acc;
}

// ---------------- kernel 3b: combine 7 partials ----------------
__global__ __launch_bounds__(256) void k_out2(float* __restrict__ out){
    const int b = blockIdx.x, tid = threadIdx.x;
    const float4* p = reinterpret_cast<const float4*>(g_part);
    float4 r = make_float4(0.f,0.f,0.f,0.f);
    #pragma unroll
    for (int q = 0; q < 7; ++q){
        float4 a = p[((size_t)q*B_ + b)*256 + tid];
        r.x += a.x; r.y += a.y; r.z += a.z; r.w += a.w;
    }
    reinterpret_cast<float4*>(out)[(size_t)b*256 + tid] = r;
}

// ---------------- launch ----------------
extern "C" void kernel_launch(void* const* d_in, const int* in_sizes, int n_in,
                              void* d_out, int out_size) {
    const float* x   = (const float*)d_in[0];
    const float* att = (const float*)d_in[1];
    const float* h   = (const float*)d_in[2];
    const float* Wa  = (const float*)d_in[3];
    const float* ba  = (const float*)d_in[4];
    const float* Wh  = (const float*)d_in[5];
    const float* bh  = (const float*)d_in[6];
    const float* Wx  = (const float*)d_in[7];
    const float* bx  = (const float*)d_in[8];
    const float* wd  = (const float*)d_in[9];
    float* out = (float*)d_out;

    cudaFuncSetAttribute(k_scores, cudaFuncAttributeMaxDynamicSharedMemorySize, SM_SZ);

    k_convert_w<<<1024, 256>>>(Wa);
    k_cvec<<<dim3(32, 8), 256>>>(h, x, Wh, Wx, bh, bx, ba);
    k_scores<<<M_/64, 512, SM_SZ>>>(att, wd);
    k_outp<<<dim3(B_, 7), 256>>>(att);
    k_out2<<<B_, 256>>>(out);
}

// round 9
// speedup vs baseline: 1.3006x; 1.1301x over previous
#include <cuda_runtime.h>
#include <cuda_bf16.h>
#include <cstdint>

#define B_  128
#define L_  196
#define D_  1024
#define M_  (B_*L_)            // 25088

// ---------------- scratch (device globals; no allocation) ----------------
__device__ float g_c[B_*D_];          // c[b,e] = att_h + att_x + 3 biases
__device__ float g_scores[M_];        // pre-softmax scores
__device__ float g_part[7*B_*D_];     // L-split partial outputs
__device__ __nv_bfloat16 g_wa[D_*D_]; // W_a2a bf16
__device__ __nv_bfloat16 g_att[(size_t)M_*D_]; // att bf16 (51.4 MB)

// ---------------- helpers ----------------
static __device__ __forceinline__ float tanh_fast(float x){
    float y; asm("tanh.approx.f32 %0, %1;" : "=f"(y) : "f"(x)); return y;
}
static __device__ __forceinline__ unsigned smem_u32(const void* p){
    return (unsigned)__cvta_generic_to_shared(p);
}
static __device__ __forceinline__ void ldsm_x4(unsigned r[4], unsigned a){
    asm volatile("ldmatrix.sync.aligned.m8n8.x4.shared.b16 {%0,%1,%2,%3}, [%4];"
        : "=r"(r[0]),"=r"(r[1]),"=r"(r[2]),"=r"(r[3]) : "r"(a));
}
static __device__ __forceinline__ void ldsm_x2(unsigned r[2], unsigned a){
    asm volatile("ldmatrix.sync.aligned.m8n8.x2.shared.b16 {%0,%1}, [%2];"
        : "=r"(r[0]),"=r"(r[1]) : "r"(a));
}
static __device__ __forceinline__ void mma16816(float d[4], const unsigned a[4], const unsigned b[2]){
    asm volatile("mma.sync.aligned.m16n8k16.row.col.f32.bf16.bf16.f32 "
        "{%0,%1,%2,%3}, {%4,%5,%6,%7}, {%8,%9}, {%0,%1,%2,%3};"
        : "+f"(d[0]),"+f"(d[1]),"+f"(d[2]),"+f"(d[3])
        : "r"(a[0]),"r"(a[1]),"r"(a[2]),"r"(a[3]),"r"(b[0]),"r"(b[1]));
}
static __device__ __forceinline__ void cp16(unsigned dst, const void* src){
    asm volatile("cp.async.cg.shared.global [%0], [%1], 16;" :: "r"(dst), "l"(src));
}
static __device__ __forceinline__ void cp_commit(){ asm volatile("cp.async.commit_group;"); }
static __device__ __forceinline__ void cp_wait0(){
    asm volatile("cp.async.wait_group 0;" ::: "memory");
}

// ---------------- kernel 0a: W_a2a fp32 -> bf16 ----------------
__global__ __launch_bounds__(256) void k_convert_w(const float* __restrict__ W){
    int i = (blockIdx.x*256 + threadIdx.x)*4;
    float4 v = *reinterpret_cast<const float4*>(W + i);
    *reinterpret_cast<__nv_bfloat162*>(&g_wa[i  ]) = __floats2bfloat162_rn(v.x, v.y);
    *reinterpret_cast<__nv_bfloat162*>(&g_wa[i+2]) = __floats2bfloat162_rn(v.z, v.w);
}
// ---------------- kernel 0b: att fp32 -> bf16 ----------------
__global__ __launch_bounds__(256) void k_convert_att(const float* __restrict__ A){
    size_t i = ((size_t)blockIdx.x*256 + threadIdx.x)*4;
    float4 v = *reinterpret_cast<const float4*>(A + i);
    *reinterpret_cast<__nv_bfloat162*>(&g_att[i  ]) = __floats2bfloat162_rn(v.x, v.y);
    *reinterpret_cast<__nv_bfloat162*>(&g_att[i+2]) = __floats2bfloat162_rn(v.z, v.w);
}

// ---------------- kernel 1: c[b,e] = h@Wh^T + x@Wx^T + (bh+bx+ba) ----------------
__global__ __launch_bounds__(256) void k_cvec(
        const float* __restrict__ h, const float* __restrict__ x,
        const float* __restrict__ Wh, const float* __restrict__ Wx,
        const float* __restrict__ bh, const float* __restrict__ bx,
        const float* __restrict__ ba){
    __shared__ float hs[4][1024];
    __shared__ float xs[4][1024];
    const int tid = threadIdx.x, wid = tid>>5, lane = tid&31;
    const int b0 = blockIdx.x*4;
    for (int i = tid; i < 1024; i += 256){
        int row = i >> 8, c = (i & 255) << 2;
        *reinterpret_cast<float4*>(&hs[row][c]) =
            *reinterpret_cast<const float4*>(h + (size_t)(b0+row)*1024 + c);
        *reinterpret_cast<float4*>(&xs[row][c]) =
            *reinterpret_cast<const float4*>(x + (size_t)(b0+row)*1024 + c);
    }
    __syncthreads();
    const int ebase = blockIdx.y*128 + wid*16;
    for (int ei = 0; ei < 16; ++ei){
        const int e = ebase + ei;
        const float4* wh4 = reinterpret_cast<const float4*>(Wh + (size_t)e*1024);
        const float4* wx4 = reinterpret_cast<const float4*>(Wx + (size_t)e*1024);
        float acc[4] = {0.f,0.f,0.f,0.f};
        #pragma unroll
        for (int it = 0; it < 8; ++it){
            const int d4 = it*32 + lane;
            float4 wv = wh4[d4], xv = wx4[d4];
            #pragma unroll
            for (int b = 0; b < 4; ++b){
                float4 hv = *reinterpret_cast<const float4*>(&hs[b][d4<<2]);
                float4 gv = *reinterpret_cast<const float4*>(&xs[b][d4<<2]);
                acc[b] += wv.x*hv.x + wv.y*hv.y + wv.z*hv.z + wv.w*hv.w;
                acc[b] += xv.x*gv.x + xv.y*gv.y + xv.z*gv.z + xv.w*gv.w;
            }
        }
        #pragma unroll
        for (int b = 0; b < 4; ++b){
            float v = acc[b];
            v += __shfl_xor_sync(0xffffffffu, v, 16);
            v += __shfl_xor_sync(0xffffffffu, v, 8);
            v += __shfl_xor_sync(0xffffffffu, v, 4);
            v += __shfl_xor_sync(0xffffffffu, v, 2);
            v += __shfl_xor_sync(0xffffffffu, v, 1);
            acc[b] = v;
        }
        if (lane < 4){
            float bias = bh[e] + bx[e] + ba[e];
            g_c[(size_t)(b0+lane)*1024 + e] = acc[lane] + bias;
        }
    }
}

// ---------------- kernel 2: fused GEMM + tanh + dot(W_d2d) -> scores ----------------
// 256 threads, 2 CTAs/SM. CTA = 64 att rows. Both A and B streamed, double-buffered,
// XOR-swizzled (pad-free). 64 flat steps: n-chunk (s>>4)*256, k-chunk (s&15)*64.
// Warp grid 2(m) x 4(n), warp tile 32m x 64n.
#define ABUF    8192               // 64 rows * 128B
#define B_OFF   16384
#define BBUF    32768              // 256 rows * 128B
#define CS_OFF  81920
#define WD_OFF  90112
#define SSC_OFF 94208
#define SM_SZ   94464

__global__ void __launch_bounds__(256, 2) k_scores(const float* __restrict__ wdd){
    extern __shared__ char sm[];
    const int tid = threadIdx.x, lane = tid & 31, wid = tid >> 5;
    const int m0 = blockIdx.x * 64;
    const int b0 = m0 / L_;
    const unsigned smb = smem_u32(sm);
    float* cs  = reinterpret_cast<float*>(sm + CS_OFF);
    float* wds = reinterpret_cast<float*>(sm + WD_OFF);
    float* ssc = reinterpret_cast<float*>(sm + SSC_OFF);

    // ---- constants ----
    {
        int b1 = (m0 + 63) / L_; if (b1 > B_-1) b1 = B_-1;
        for (int i = tid; i < 2048; i += 256){
            int w = i >> 10, e = i & 1023;
            cs[i] = g_c[(size_t)(w ? b1 : b0)*1024 + e];
        }
        for (int i = tid; i < 1024; i += 256) wds[i] = wdd[i];
        if (tid < 64) ssc[tid] = 0.f;
    }

    const int m_off = (wid >> 2) * 32;        // 0,32
    const int n_off = (wid & 3) * 64;         // 0..192 within 256-wide n-chunk
    const unsigned v  = (unsigned)(lane & 7); // swizzle key (row&7 for both operands)
    const unsigned ua = (unsigned)(lane >> 4);
    const unsigned ub = (unsigned)((lane >> 3) & 1);
    const unsigned a_row = smb + (unsigned)((m_off + (lane & 15)) * 128);
    const unsigned b_row = smb + B_OFF + (unsigned)((n_off + (lane & 7)) * 128);

    const float* crow[2][2]; int rowl[2][2];
    #pragma unroll
    for (int mt = 0; mt < 2; ++mt)
        #pragma unroll
        for (int hf = 0; hf < 2; ++hf){
            const int r = m_off + mt*16 + (lane >> 2) + hf*8;
            rowl[mt][hf] = r;
            crow[mt][hf] = cs + (((m0 + r)/L_ != b0) ? 1024 : 0);
        }

    // tile loader: step t -> n0=(t>>4)*256, kk=(t&15)*64; XOR-swizzled stores
    auto load_step = [&](int t, int buf){
        const int n0 = (t >> 4) * 256, kk = (t & 15) * 64;
        #pragma unroll
        for (int i = 0; i < 2; ++i){             // A: 64x64 bf16 = 512 granules
            const int idx = tid + i*256;
            const int r = idx >> 3, c = idx & 7;
            cp16(smb + (unsigned)(buf*ABUF + r*128 + (((unsigned)c ^ (r&7))<<4)),
                 g_att + ((size_t)(m0 + r) << 10) + kk + c*8);
        }
        #pragma unroll
        for (int i = 0; i < 8; ++i){             // B: 256x64 bf16 = 2048 granules
            const int idx = tid + i*256;
            const int r = idx >> 3, c = idx & 7;
            cp16(smb + B_OFF + (unsigned)(buf*BBUF + r*128 + (((unsigned)c ^ (r&7))<<4)),
                 g_wa + ((size_t)(n0 + r) << 10) + kk + c*8);
        }
    };

    float acc[2][8][4];
    load_step(0, 0);
    cp_commit();

    for (int s = 0; s < 64; ++s){
        const int kc = s & 15;
        cp_wait0();                  // step-s tiles arrived
        __syncthreads();             // all warps done reading buffer (s+1)&1
        if (s < 63){ load_step(s+1, (s+1)&1); cp_commit(); }

        if (kc == 0){
            #pragma unroll
            for (int mt = 0; mt < 2; ++mt)
                #pragma unroll
                for (int nt = 0; nt < 8; ++nt)
                    #pragma unroll
                    for (int i = 0; i < 4; ++i) acc[mt][nt][i] = 0.f;
        }
        const unsigned ao = (unsigned)((s & 1) * ABUF);
        const unsigned bo = (unsigned)((s & 1) * BBUF);
        #pragma unroll
        for (int ks = 0; ks < 4; ++ks){
            unsigned af[2][4], bf[8][2];
            const unsigned ca = (((unsigned)(2*ks) + ua) ^ v) << 4;
            #pragma unroll
            for (int mt = 0; mt < 2; ++mt)
                ldsm_x4(af[mt], a_row + ao + (unsigned)(mt*2048) + ca);
            const unsigned cb = (((unsigned)(2*ks) + ub) ^ v) << 4;
            #pragma unroll
            for (int nt = 0; nt < 8; ++nt)
                ldsm_x2(bf[nt], b_row + bo + (unsigned)(nt*1024) + cb);
            #pragma unroll
            for (int mt = 0; mt < 2; ++mt)
                #pragma unroll
                for (int nt = 0; nt < 8; ++nt)
                    mma16816(acc[mt][nt], af[mt], bf[nt]);
        }

        if (kc == 15){   // n-chunk complete: fused tanh*W_d2d epilogue
            const int n0c = (s >> 4) * 256;
            #pragma unroll
            for (int mt = 0; mt < 2; ++mt)
                #pragma unroll
                for (int hf = 0; hf < 2; ++hf){
                    float vsum = 0.f;
                    const float* cr = crow[mt][hf];
                    #pragma unroll
                    for (int nt = 0; nt < 8; ++nt){
                        const int e0 = n0c + n_off + nt*8 + (lane & 3)*2;
                        vsum += tanh_fast(acc[mt][nt][hf*2+0] + cr[e0  ]) * wds[e0  ];
                        vsum += tanh_fast(acc[mt][nt][hf*2+1] + cr[e0+1]) * wds[e0+1];
                    }
                    vsum += __shfl_xor_sync(0xffffffffu, vsum, 1);
                    vsum += __shfl_xor_sync(0xffffffffu, vsum, 2);
                    if ((lane & 3) == 0) atomicAdd(&ssc[rowl[mt][hf]], vsum);
                }
        }
    }
    __syncthreads();
    if (tid < 64) g_scores[m0 + tid] = ssc[tid];   // b_d2d dropped (softmax shift-invariant)
}

// ---------------- kernel 3a: softmax + L-split(7) weighted partial sums ----------------
__global__ __launch_bounds__(256) void k_outp(const float* __restrict__ att){
    __shared__ float sc[256];
    __shared__ float red[256];
    const int b = blockIdx.x, q = blockIdx.y, tid = threadIdx.x;
    const float s = (tid < L_) ? g_scores[b*L_ + tid] : -1e30f;
    red[tid] = s; __syncthreads();
    #pragma unroll
    for (int o = 128; o > 0; o >>= 1){
        if (tid < o) red[tid] = fmaxf(red[tid], red[tid+o]);
        __syncthreads();
    }
    const float mx = red[0]; __syncthreads();
    const float e = (tid < L_) ? __expf(s - mx) : 0.f;
    sc[tid] = e; red[tid] = e; __syncthreads();
    #pragma unroll
    for (int o = 128; o > 0; o >>= 1){
        if (tid < o) red[tid] += red[tid+o];
        __syncthreads();
    }
    const float inv = 1.f / red[0];
    __syncthreads();

    const float4* ap = reinterpret_cast<const float4*>(att)
                     + (size_t)b*L_*256 + (size_t)q*28*256 + tid;
    float4 acc = make_float4(0.f,0.f,0.f,0.f);
    #pragma unroll 7
    for (int l = 0; l < 28; ++l){
        float4 vv = ap[(size_t)l*256];
        const float wl = sc[q*28 + l] * inv;
        acc.x += wl*vv.x; acc.y += wl*vv.y; acc.z += wl*vv.z; acc.w += wl*vv.w;
    }
    reinterpret_cast<float4*>(g_part)[((size_t)q*B_ + b)*256 + tid] = acc;
}

// ---------------- kernel 3b: combine 7 partials ----------------
__global__ __launch_bounds__(256) void k_out2(float* __restrict__ out){
    const int b = blockIdx.x, tid = threadIdx.x;
    const float4* p = reinterpret_cast<const float4*>(g_part);
    float4 r = make_float4(0.f,0.f,0.f,0.f);
    #pragma unroll
    for (int q = 0; q < 7; ++q){
        float4 a = p[((size_t)q*B_ + b)*256 + tid];
        r.x += a.x; r.y += a.y; r.z += a.z; r.w += a.w;
    }
    reinterpret_cast<float4*>(out)[(size_t)b*256 + tid] = r;
}

// ---------------- launch ----------------
extern "C" void kernel_launch(void* const* d_in, const int* in_sizes, int n_in,
                              void* d_out, int out_size) {
    const float* x   = (const float*)d_in[0];
    const float* att = (const float*)d_in[1];
    const float* h   = (const float*)d_in[2];
    const float* Wa  = (const float*)d_in[3];
    const float* ba  = (const float*)d_in[4];
    const float* Wh  = (const float*)d_in[5];
    const float* bh  = (const float*)d_in[6];
    const float* Wx  = (const float*)d_in[7];
    const float* bx  = (const float*)d_in[8];
    const float* wd  = (const float*)d_in[9];
    float* out = (float*)d_out;

    cudaFuncSetAttribute(k_scores, cudaFuncAttributeMaxDynamicSharedMemorySize, SM_SZ);

    k_convert_w<<<1024, 256>>>(Wa);
    k_convert_att<<<(int)(((size_t)M_*D_)/1024), 256>>>(att);
    k_cvec<<<dim3(32, 8), 256>>>(h, x, Wh, Wx, bh, bx, ba);
    k_scores<<<M_/64, 256, SM_SZ>>>(wd);
    k_outp<<<dim3(B_, 7), 256>>>(att);
    k_out2<<<B_, 256>>>(out);
}